// round 1
// baseline (speedup 1.0000x reference)
#include <cuda_runtime.h>

#define BATCH 32
#define HW    4096
#define HH    64
#define WW    64
#define CIN   960
#define C3    96
#define NGROUP 12

// ---------- scratch (static device allocations; no cudaMalloc) ----------
__device__ float g_stats[(long)BATCH * HW * 6];        // per token: (mean,rstd) x 3 segments
__device__ float g_qkv [(long)BATCH * C3 * HW];        // 48 MB
__device__ float g_m3  [(long)BATCH * C3 * HW];        // 48 MB
__device__ float g_m5  [(long)BATCH * C3 * HW];        // 48 MB
__device__ float g_vk  [BATCH * NGROUP * 72];
__device__ float g_att [(long)BATCH * C3 * HW];        // 48 MB

// ======================= LN statistics (warp per token) =======================
template<int R, int C>
__device__ __forceinline__ float2 stat_seg(const float* __restrict__ x, int lane)
{
    float s = 0.f, sq = 0.f;
#pragma unroll
    for (int r = 0; r < R; r++) {
        float v = x[lane + 32 * r];
        s += v; sq += v * v;
    }
#pragma unroll
    for (int off = 16; off > 0; off >>= 1) {
        s  += __shfl_xor_sync(0xffffffffu, s,  off);
        sq += __shfl_xor_sync(0xffffffffu, sq, off);
    }
    float mean = s * (1.0f / C);
    float var  = sq * (1.0f / C) - mean * mean;
    return make_float2(mean, rsqrtf(var + 1e-6f));
}

__global__ void stats_kernel(const float* __restrict__ x1,
                             const float* __restrict__ x2,
                             const float* __restrict__ x3)
{
    long t = (long)blockIdx.x * 4 + (threadIdx.x >> 5);
    int lane = threadIdx.x & 31;
    float2 s1 = stat_seg<6, 192>(x1 + t * 192, lane);
    float2 s2 = stat_seg<8, 256>(x2 + t * 256, lane);
    float2 s3 = stat_seg<16,512>(x3 + t * 512, lane);
    if (lane == 0) {
        float* o = g_stats + t * 6;
        o[0] = s1.x; o[1] = s1.y;
        o[2] = s2.x; o[3] = s2.y;
        o[4] = s3.x; o[5] = s3.y;
    }
}

// ======================= QKV GEMM (LN fused into B-load) =======================
// out[b][o][n] = sum_c qkv_w[o][c] * LN(xc)[b][n][c]
// tile: 96(M) x 64(N), K-step 32. Segment boundaries (192,448) are multiples of 32.
__global__ void qkv_gemm(const float* __restrict__ W,
                         const float* __restrict__ x1, const float* __restrict__ g1, const float* __restrict__ b1,
                         const float* __restrict__ x2, const float* __restrict__ g2, const float* __restrict__ b2,
                         const float* __restrict__ x3, const float* __restrict__ g3, const float* __restrict__ b3)
{
    int b  = blockIdx.y;
    int n0 = blockIdx.x * 64;
    __shared__ float As[96][32];
    __shared__ float Bs[32][65];

    int tid = threadIdx.x;
    int tx = tid & 15, ty = tid >> 4;

    float acc[6][4];
#pragma unroll
    for (int i = 0; i < 6; i++)
#pragma unroll
        for (int j = 0; j < 4; j++) acc[i][j] = 0.f;

    for (int kt = 0; kt < 960; kt += 32) {
        // segment for this k-slab (uniform across block)
        const float *xs, *ga, *be; int off, Cs, seg;
        if (kt < 192)      { xs = x1; ga = g1; be = b1; off = 0;   Cs = 192; seg = 0; }
        else if (kt < 448) { xs = x2; ga = g2; be = b2; off = 192; Cs = 256; seg = 1; }
        else               { xs = x3; ga = g3; be = b3; off = 448; Cs = 512; seg = 2; }

        // A: 96x32 of W
#pragma unroll
        for (int p = 0; p < 3; p++) {
            int idx = tid + p * 256;
            int row = idx >> 3, q = idx & 7;
            float4 a4 = *(const float4*)(W + (long)row * 960 + kt + q * 4);
            As[row][q*4+0] = a4.x; As[row][q*4+1] = a4.y;
            As[row][q*4+2] = a4.z; As[row][q*4+3] = a4.w;
        }
        // B: 64 tokens x 32 channels, LN applied on the fly, stored transposed
#pragma unroll
        for (int p = 0; p < 2; p++) {
            int idx = tid + p * 256;
            int n = idx >> 3, q = idx & 7;
            long tok = (long)b * HW + n0 + n;
            float4 raw = *(const float4*)(xs + tok * Cs + (kt - off) + q * 4);
            float2 st  = *(const float2*)(g_stats + tok * 6 + seg * 2);
            int kb = kt - off + q * 4;
            Bs[q*4+0][n] = (raw.x - st.x) * st.y * ga[kb+0] + be[kb+0];
            Bs[q*4+1][n] = (raw.y - st.x) * st.y * ga[kb+1] + be[kb+1];
            Bs[q*4+2][n] = (raw.z - st.x) * st.y * ga[kb+2] + be[kb+2];
            Bs[q*4+3][n] = (raw.w - st.x) * st.y * ga[kb+3] + be[kb+3];
        }
        __syncthreads();
#pragma unroll
        for (int kk = 0; kk < 32; kk++) {
            float a[6], bb[4];
#pragma unroll
            for (int i = 0; i < 6; i++) a[i] = As[ty*6+i][kk];
#pragma unroll
            for (int j = 0; j < 4; j++) bb[j] = Bs[kk][tx*4+j];
#pragma unroll
            for (int i = 0; i < 6; i++)
#pragma unroll
                for (int j = 0; j < 4; j++) acc[i][j] += a[i] * bb[j];
        }
        __syncthreads();
    }
#pragma unroll
    for (int i = 0; i < 6; i++) {
        int m = ty * 6 + i;
        float4 r; r.x = acc[i][0]; r.y = acc[i][1]; r.z = acc[i][2]; r.w = acc[i][3];
        *(float4*)(g_qkv + ((long)b * C3 + m) * HW + n0 + tx * 4) = r;
    }
}

// ======================= fused dwconv3/5 + grouped pointwise =======================
__global__ void conv_kernel(const float* __restrict__ dw3, const float* __restrict__ pw3,
                            const float* __restrict__ dw5, const float* __restrict__ pw5)
{
    int b  = blockIdx.z;
    int g  = blockIdx.y;       // pw group 0..11, channels g*8..g*8+7
    int r0 = blockIdx.x * 8;   // output row strip
    __shared__ float sin[8][12][68];
    __shared__ float w3[8][9], w5[8][25], p3[8][8], p5[8][8];
    int tid = threadIdx.x;
    const float* src = g_qkv + ((long)b * C3 + g * 8) * HW;

    for (int idx = tid; idx < 8 * 12 * 68; idx += 256) {
        int c = idx / (12 * 68);
        int rem = idx % (12 * 68);
        int r = rem / 68, col = rem % 68;
        int gr = r0 + r - 2, gc = col - 2;
        float v = 0.f;
        if (gr >= 0 && gr < HH && gc >= 0 && gc < WW)
            v = src[(long)c * HW + gr * WW + gc];
        sin[c][r][col] = v;
    }
    if (tid < 72)  w3[tid/9][tid%9]   = dw3[(g*8 + tid/9)*9  + tid%9];
    if (tid < 200) w5[tid/25][tid%25] = dw5[(g*8 + tid/25)*25 + tid%25];
    if (tid < 64)  { p3[tid/8][tid%8] = pw3[(g*8 + tid/8)*8 + tid%8];
                     p5[tid/8][tid%8] = pw5[(g*8 + tid/8)*8 + tid%8]; }
    __syncthreads();

#pragma unroll
    for (int pp = 0; pp < 2; pp++) {
        int pos = tid + pp * 256;
        int lr = pos >> 6, lc = pos & 63;
        float d3[8], d5[8];
#pragma unroll
        for (int i = 0; i < 8; i++) {
            float s3 = 0.f, s5 = 0.f;
#pragma unroll
            for (int ky = 0; ky < 3; ky++)
#pragma unroll
                for (int kx = 0; kx < 3; kx++)
                    s3 += w3[i][ky*3+kx] * sin[i][lr+1+ky][lc+1+kx];
#pragma unroll
            for (int ky = 0; ky < 5; ky++)
#pragma unroll
                for (int kx = 0; kx < 5; kx++)
                    s5 += w5[i][ky*5+kx] * sin[i][lr+ky][lc+kx];
            d3[i] = s3; d5[i] = s5;
        }
        long obase = ((long)b * C3 + g * 8) * HW + (long)(r0 + lr) * WW + lc;
#pragma unroll
        for (int o = 0; o < 8; o++) {
            float a3 = 0.f, a5 = 0.f;
#pragma unroll
            for (int i = 0; i < 8; i++) { a3 += p3[o][i] * d3[i]; a5 += p5[o][i] * d5[i]; }
            g_m3[obase + (long)o * HW] = a3;
            g_m5[obase + (long)o * HW] = a5;
        }
    }
}

// ======================= vk = [v;1] @ relu(k)^T  (9x8 per (b,g)) =======================
__global__ void vk_kernel()
{
    int g = blockIdx.x, b = blockIdx.y;
    const float* src; int base;
    if (g < 4)      { src = g_qkv; base = 24 * g; }
    else if (g < 8) { src = g_m3;  base = 24 * (g - 4); }
    else            { src = g_m5;  base = 24 * (g - 8); }
    src += (long)b * C3 * HW + (long)base * HW;

    float acc[72];
#pragma unroll
    for (int i = 0; i < 72; i++) acc[i] = 0.f;

    for (int n = threadIdx.x; n < HW; n += 256) {
        float kv[8], vv[8];
#pragma unroll
        for (int e = 0; e < 8; e++) kv[e] = fmaxf(src[(long)(8 + e) * HW + n], 0.f);
#pragma unroll
        for (int d = 0; d < 8; d++) vv[d] = src[(long)(16 + d) * HW + n];
#pragma unroll
        for (int d = 0; d < 8; d++)
#pragma unroll
            for (int e = 0; e < 8; e++) acc[d * 8 + e] += vv[d] * kv[e];
#pragma unroll
        for (int e = 0; e < 8; e++) acc[64 + e] += kv[e];
    }

    __shared__ float red[8][72];
    int lane = threadIdx.x & 31, warp = threadIdx.x >> 5;
#pragma unroll
    for (int i = 0; i < 72; i++) {
        float v = acc[i];
#pragma unroll
        for (int off = 16; off > 0; off >>= 1) v += __shfl_xor_sync(0xffffffffu, v, off);
        if (lane == 0) red[warp][i] = v;
    }
    __syncthreads();
    if (threadIdx.x < 72) {
        float s = 0.f;
#pragma unroll
        for (int w = 0; w < 8; w++) s += red[w][threadIdx.x];
        g_vk[(b * NGROUP + g) * 72 + threadIdx.x] = s;
    }
}

// ======================= att = (vk @ relu(q)) num/den =======================
__global__ void att_kernel()
{
    int b = blockIdx.z, g = blockIdx.y;
    int n = blockIdx.x * 256 + threadIdx.x;
    __shared__ float vk[72];
    if (threadIdx.x < 72) vk[threadIdx.x] = g_vk[(b * NGROUP + g) * 72 + threadIdx.x];
    __syncthreads();

    const float* src; int base;
    if (g < 4)      { src = g_qkv; base = 24 * g; }
    else if (g < 8) { src = g_m3;  base = 24 * (g - 4); }
    else            { src = g_m5;  base = 24 * (g - 8); }
    src += (long)b * C3 * HW + (long)base * HW;

    float q[8];
#pragma unroll
    for (int e = 0; e < 8; e++) q[e] = fmaxf(src[(long)e * HW + n], 0.f);
    float den = 1e-15f;
#pragma unroll
    for (int e = 0; e < 8; e++) den += vk[64 + e] * q[e];
    float inv = 1.0f / den;
    float* dst = g_att + ((long)b * C3 + g * 8) * HW + n;
#pragma unroll
    for (int d = 0; d < 8; d++) {
        float num = 0.f;
#pragma unroll
        for (int e = 0; e < 8; e++) num += vk[d * 8 + e] * q[e];
        dst[(long)d * HW] = num * inv;
    }
}

// ======================= proj GEMM + BN + transpose + residual + split =======================
// tile 64(o) x 64(n), K=96 in one shot. 64-wide o-tiles never cross {192,448}.
__global__ void proj_kernel(const float* __restrict__ W,
                            const float* __restrict__ bn_g, const float* __restrict__ bn_b,
                            const float* __restrict__ bn_m, const float* __restrict__ bn_v,
                            const float* __restrict__ x1, const float* __restrict__ x2,
                            const float* __restrict__ x3, float* __restrict__ out)
{
    int b  = blockIdx.z;
    int n0 = blockIdx.y * 64;
    int o0 = blockIdx.x * 64;
    __shared__ float Ws[64][96];
    __shared__ float At[96 * 64];
    int tid = threadIdx.x, tx = tid & 15, ty = tid >> 4;

#pragma unroll
    for (int p = 0; p < 6; p++) {
        int idx = tid + p * 256;
        int r = idx / 24, q = idx % 24;
        float4 w4 = *(const float4*)(W + (long)(o0 + r) * 96 + q * 4);
        *(float4*)&Ws[r][q * 4] = w4;
    }
    const float* A = g_att + (long)b * C3 * HW;
#pragma unroll
    for (int p = 0; p < 6; p++) {
        int idx = tid + p * 256;
        int c = idx >> 4, q = idx & 15;
        float4 a4 = *(const float4*)(A + (long)c * HW + n0 + q * 4);
        *(float4*)&At[c * 64 + q * 4] = a4;
    }
    __syncthreads();

    float acc[4][4];
#pragma unroll
    for (int i = 0; i < 4; i++)
#pragma unroll
        for (int j = 0; j < 4; j++) acc[i][j] = 0.f;
#pragma unroll 8
    for (int c = 0; c < 96; c++) {
        float a[4], bb[4];
#pragma unroll
        for (int i = 0; i < 4; i++) a[i] = Ws[ty * 4 + i][c];
#pragma unroll
        for (int j = 0; j < 4; j++) bb[j] = At[c * 64 + tx * 4 + j];
#pragma unroll
        for (int i = 0; i < 4; i++)
#pragma unroll
            for (int j = 0; j < 4; j++) acc[i][j] += a[i] * bb[j];
    }
    __syncthreads();

    // BN + transpose into smem (reuse At)
#pragma unroll
    for (int i = 0; i < 4; i++) {
        int o = o0 + ty * 4 + i;
        float sc = bn_g[o] * rsqrtf(bn_v[o] + 1e-5f);
        float mb = bn_m[o], bb2 = bn_b[o];
#pragma unroll
        for (int j = 0; j < 4; j++)
            At[(tx * 4 + j) * 64 + (ty * 4 + i)] = (acc[i][j] - mb) * sc + bb2;
    }
    __syncthreads();

    const float* xs; int Cs, off; long obase;
    if (o0 < 192)      { xs = x1; Cs = 192; off = 0;   obase = 0; }
    else if (o0 < 448) { xs = x2; Cs = 256; off = 192; obase = (long)BATCH * HW * 192; }
    else               { xs = x3; Cs = 512; off = 448; obase = (long)BATCH * HW * (192 + 256); }

    for (int idx = tid; idx < 4096; idx += 256) {
        int nl = idx >> 6, ol = idx & 63;
        long tok  = (long)b * HW + n0 + nl;
        long addr = tok * Cs + (o0 - off) + ol;
        out[obase + addr] = At[nl * 64 + ol] + xs[addr];
    }
}

// ======================= launch =======================
extern "C" void kernel_launch(void* const* d_in, const int* in_sizes, int n_in,
                              void* d_out, int out_size)
{
    const float *x1, *g1, *b1, *x2, *g2, *b2, *x3, *g3, *b3;
    if (in_sizes[1] < 100000) {   // interleaved dict order: x1,ln_g1,ln_b1,x2,...
        x1 = (const float*)d_in[0]; g1 = (const float*)d_in[1]; b1 = (const float*)d_in[2];
        x2 = (const float*)d_in[3]; g2 = (const float*)d_in[4]; b2 = (const float*)d_in[5];
        x3 = (const float*)d_in[6]; g3 = (const float*)d_in[7]; b3 = (const float*)d_in[8];
    } else {                      // grouped order: x1,x2,x3,ln_g1,ln_b1,...
        x1 = (const float*)d_in[0]; x2 = (const float*)d_in[1]; x3 = (const float*)d_in[2];
        g1 = (const float*)d_in[3]; b1 = (const float*)d_in[4];
        g2 = (const float*)d_in[5]; b2 = (const float*)d_in[6];
        g3 = (const float*)d_in[7]; b3 = (const float*)d_in[8];
    }
    const float* qkv_w  = (const float*)d_in[9];
    const float* dw3    = (const float*)d_in[10];
    const float* pw3    = (const float*)d_in[11];
    const float* dw5    = (const float*)d_in[12];
    const float* pw5    = (const float*)d_in[13];
    const float* proj_w = (const float*)d_in[14];
    const float* bn_g   = (const float*)d_in[15];
    const float* bn_b   = (const float*)d_in[16];
    const float* bn_m   = (const float*)d_in[17];
    const float* bn_v   = (const float*)d_in[18];
    float* out = (float*)d_out;

    stats_kernel<<<BATCH * HW / 4, 128>>>(x1, x2, x3);
    qkv_gemm<<<dim3(64, BATCH), 256>>>(qkv_w, x1, g1, b1, x2, g2, b2, x3, g3, b3);
    conv_kernel<<<dim3(8, 12, BATCH), 256>>>(dw3, pw3, dw5, pw5);
    vk_kernel<<<dim3(12, BATCH), 256>>>();
    att_kernel<<<dim3(16, 12, BATCH), 256>>>();
    proj_kernel<<<dim3(15, 64, BATCH), 256>>>(proj_w, bn_g, bn_b, bn_m, bn_v, x1, x2, x3, out);
}